// round 8
// baseline (speedup 1.0000x reference)
#include <cuda_runtime.h>
#include <cstdint>

// ---------------------------------------------------------------------------
// PrunedGroupSum: y[b,g] = (sum over contiguous column group g of x[b,:]) / 20
//   x:           [B, D] float32   (B=1024, D=262144 -> 1 GiB, streaming)
//   group_sizes: [K]    int32     (K=1000, sums to D)
//   out:         [B, K] float32
//
// R8: bulk-async (TMA) producer/consumer pipeline to break the register-file
// in-flight ceiling (R7: 80.8% DRAM, reg-capped at ~160KB peak in flight).
// Block = (group g, 32 rows): warp 4 = producer issues cp.async.bulk
// global->shared per row (16B-aligned over-fetch, masked on consume),
// 3-stage x 32KB smem ring with mbarrier full/empty; warps 0-3 consume
// 8 rows each from smem and butterfly-reduce. Producer never stalls on the
// reduce -> loads stay outstanding ~100% of the time. No atomics.
// ---------------------------------------------------------------------------

#define MAX_K          4096
#define NSTAGE         3
#define CHUNK_COLS     256
#define ROWS_PER_BLOCK 32
#define ROWS_PER_WARP  8
#define NCONS_WARPS    4
#define NTHREADS       160   // 4 consumer warps + 1 producer warp

#define STAGE_FLOATS   (ROWS_PER_BLOCK * CHUNK_COLS)          // 8192 floats = 32KB
#define SMEM_FLOATS    (NSTAGE * STAGE_FLOATS)                // 96KB of stages
#define SMEM_BYTES     (SMEM_FLOATS * 4 + 2 * NSTAGE * 8 + 16)

__device__ int g_offsets[MAX_K + 1];

// 1-block Hillis-Steele inclusive scan of group_sizes (K <= 1024; K=1000 here).
__global__ void pgs_scan_kernel(const int* __restrict__ gs, int K) {
    __shared__ int sh[1024];
    int t = threadIdx.x;
    int v = (t < K) ? gs[t] : 0;
    sh[t] = v;
    __syncthreads();
#pragma unroll
    for (int off = 1; off < 1024; off <<= 1) {
        int add = (t >= off) ? sh[t - off] : 0;
        __syncthreads();
        sh[t] += add;
        __syncthreads();
    }
    if (t == 0) g_offsets[0] = 0;
    if (t < K) g_offsets[t + 1] = sh[t];
}

// ---- PTX helpers ----------------------------------------------------------

__device__ __forceinline__ uint32_t smem_u32(const void* p) {
    uint32_t a;
    asm("{ .reg .u64 t; cvta.to.shared.u64 t, %1; cvt.u32.u64 %0, t; }"
        : "=r"(a) : "l"(p));
    return a;
}
__device__ __forceinline__ void mbar_init(uint32_t a, uint32_t cnt) {
    asm volatile("mbarrier.init.shared.b64 [%0], %1;" :: "r"(a), "r"(cnt) : "memory");
}
__device__ __forceinline__ void mbar_expect_tx(uint32_t a, uint32_t bytes) {
    asm volatile("mbarrier.arrive.expect_tx.shared.b64 _, [%0], %1;"
                 :: "r"(a), "r"(bytes) : "memory");
}
__device__ __forceinline__ void mbar_arrive(uint32_t a) {
    asm volatile("mbarrier.arrive.shared.b64 _, [%0];" :: "r"(a) : "memory");
}
__device__ __forceinline__ void mbar_wait_acq(uint32_t a, uint32_t parity) {
    asm volatile(
        "{\n\t"
        ".reg .pred P1;\n\t"
        "WAIT_LOOP_%=:\n\t"
        "mbarrier.try_wait.parity.acquire.cta.shared::cta.b64 P1, [%0], %1, 0x989680;\n\t"
        "@P1 bra.uni WAIT_DONE_%=;\n\t"
        "bra.uni WAIT_LOOP_%=;\n\t"
        "WAIT_DONE_%=:\n\t"
        "}" :: "r"(a), "r"(parity) : "memory");
}
__device__ __forceinline__ void mbar_wait_rlx(uint32_t a, uint32_t parity) {
    asm volatile(
        "{\n\t"
        ".reg .pred P1;\n\t"
        "WAIT_LOOP_%=:\n\t"
        "mbarrier.try_wait.parity.relaxed.cta.shared::cta.b64 P1, [%0], %1, 0x989680;\n\t"
        "@P1 bra.uni WAIT_DONE_%=;\n\t"
        "bra.uni WAIT_LOOP_%=;\n\t"
        "WAIT_DONE_%=:\n\t"
        "}" :: "r"(a), "r"(parity) : "memory");
}
__device__ __forceinline__ void bulk_g2s(uint32_t dst, const void* src,
                                         uint32_t bytes, uint32_t mbar) {
    asm volatile(
        "cp.async.bulk.shared::cluster.global.mbarrier::complete_tx::bytes "
        "[%0], [%1], %2, [%3];"
        :: "r"(dst), "l"(src), "r"(bytes), "r"(mbar) : "memory");
}

__device__ __forceinline__ float hsum4(float4 v) {
    return (v.x + v.y) + (v.z + v.w);
}

// ---- main pipelined kernel --------------------------------------------------

__global__ __launch_bounds__(NTHREADS) void pgs_pipe_kernel(
    const float* __restrict__ x,
    float* __restrict__ out,
    int D, int K, int B)
{
    extern __shared__ float smem[];
    // barriers live after the stage buffers (8B-aligned offset: 96KB)
    uint64_t* bars = reinterpret_cast<uint64_t*>(smem + SMEM_FLOATS);
    // bars[0..NSTAGE): full,  bars[NSTAGE..2*NSTAGE): empty

    int tid  = threadIdx.x;
    int warp = tid >> 5;
    int lane = tid & 31;

    int g    = blockIdx.x;
    int row0 = blockIdx.y * ROWS_PER_BLOCK;
    int nr   = B - row0;
    if (nr > ROWS_PER_BLOCK) nr = ROWS_PER_BLOCK;

    int s = g_offsets[g];
    int e = g_offsets[g + 1];
    int s16 = s & ~3;
    int e16 = (e + 3) & ~3;           // requires D % 4 == 0 (holds: D=262144)
    int span = e16 - s16;
    int nch  = (span + CHUNK_COLS - 1) / CHUNK_COLS;

    uint32_t smem_base = smem_u32(smem);
    uint32_t full0  = smem_u32(&bars[0]);
    uint32_t empty0 = smem_u32(&bars[NSTAGE]);

    if (tid == 0) {
#pragma unroll
        for (int st = 0; st < NSTAGE; st++) {
            mbar_init(full0  + st * 8, 1);                     // producer lane0
            mbar_init(empty0 + st * 8, NCONS_WARPS * 32);      // all consumers
        }
    }
    __syncthreads();

    if (warp == NCONS_WARPS) {
        // ------------------ producer warp ------------------
        int pstage = 0, pphase = 1;    // phase=1: first NSTAGE empty-waits pass
        for (int ci = 0; ci < nch; ci++) {
            mbar_wait_rlx(empty0 + pstage * 8, (uint32_t)pphase);
            int cbase  = s16 + ci * CHUNK_COLS;
            int span_c = e16 - cbase;
            if (span_c > CHUNK_COLS) span_c = CHUNK_COLS;
            uint32_t bytes = (uint32_t)nr * (uint32_t)span_c * 4u;
            if (lane == 0) mbar_expect_tx(full0 + pstage * 8, bytes);
            __syncwarp();
            if (lane < nr) {
                uint32_t dst = smem_base +
                    (uint32_t)(pstage * STAGE_FLOATS + lane * CHUNK_COLS) * 4u;
                const float* src = x + (size_t)(row0 + lane) * (size_t)D + cbase;
                bulk_g2s(dst, src, (uint32_t)span_c * 4u, full0 + pstage * 8);
            }
            if (++pstage == NSTAGE) { pstage = 0; pphase ^= 1; }
        }
    } else {
        // ------------------ consumer warps ------------------
        float acc[ROWS_PER_WARP];
#pragma unroll
        for (int r = 0; r < ROWS_PER_WARP; r++) acc[r] = 0.0f;

        int cstage = 0, cphase = 0;
        for (int ci = 0; ci < nch; ci++) {
            mbar_wait_acq(full0 + cstage * 8, (uint32_t)cphase);

            int cbase  = s16 + ci * CHUNK_COLS;
            int span_c = e16 - cbase;
            if (span_c > CHUNK_COLS) span_c = CHUNK_COLS;
            const float* stage = smem + cstage * STAGE_FLOATS;

#pragma unroll
            for (int r = 0; r < ROWS_PER_WARP; r++) {
                int row = warp * ROWS_PER_WARP + r;
                if (row >= nr) break;
                const float* rp = stage + row * CHUNK_COLS;
#pragma unroll
                for (int it = 0; it < 2; it++) {
                    int lcol = it * 128 + lane * 4;
                    if (lcol < span_c) {
                        float4 v = *reinterpret_cast<const float4*>(rp + lcol);
                        int gc = cbase + lcol;
                        if (gc >= s && gc + 3 < e) {
                            acc[r] += hsum4(v);
                        } else {
                            if (gc     >= s && gc     < e) acc[r] += v.x;
                            if (gc + 1 >= s && gc + 1 < e) acc[r] += v.y;
                            if (gc + 2 >= s && gc + 2 < e) acc[r] += v.z;
                            if (gc + 3 >= s && gc + 3 < e) acc[r] += v.w;
                        }
                    }
                }
            }

            mbar_arrive(empty0 + cstage * 8);
            if (++cstage == NSTAGE) { cstage = 0; cphase ^= 1; }
        }

        // butterfly reduce + store
#pragma unroll
        for (int r = 0; r < ROWS_PER_WARP; r++) {
#pragma unroll
            for (int o = 16; o > 0; o >>= 1)
                acc[r] += __shfl_xor_sync(0xffffffffu, acc[r], o);
        }
        if (lane == 0) {
            const float inv_tau = 1.0f / 20.0f;
            int rw0 = row0 + warp * ROWS_PER_WARP;
#pragma unroll
            for (int r = 0; r < ROWS_PER_WARP; r++) {
                int row = rw0 + r;
                if (row < B && (warp * ROWS_PER_WARP + r) < nr)
                    out[(size_t)row * (size_t)K + g] = acc[r] * inv_tau;
            }
        }
    }
}

extern "C" void kernel_launch(void* const* d_in, const int* in_sizes, int n_in,
                              void* d_out, int out_size) {
    const float* x  = (const float*)d_in[0];
    const int*   gs = (const int*)d_in[1];

    int K = in_sizes[1];
    int B = out_size / K;
    int D = in_sizes[0] / B;

    float* out = (float*)d_out;

    cudaFuncSetAttribute(pgs_pipe_kernel,
                         cudaFuncAttributeMaxDynamicSharedMemorySize, SMEM_BYTES);

    pgs_scan_kernel<<<1, 1024>>>(gs, K);

    dim3 grid(K, (B + ROWS_PER_BLOCK - 1) / ROWS_PER_BLOCK);
    pgs_pipe_kernel<<<grid, NTHREADS, SMEM_BYTES>>>(x, out, D, K, B);
}

// round 9
// speedup vs baseline: 2.4471x; 2.4471x over previous
#include <cuda_runtime.h>
#include <cstdint>

// ---------------------------------------------------------------------------
// PrunedGroupSum: y[b,g] = (sum over contiguous column group g of x[b,:]) / 20
//   x:           [B, D] float32   (B=1024, D=262144 -> 1 GiB, streaming)
//   group_sizes: [K]    int32     (K=1000, sums to D)
//   out:         [B, K] float32
//
// R9: R7 structure (block = (group, 32 rows), warp = 8-row slice, 8
// independent LDG.128 per tile) + software-pipelined main loop: the two
// load buffers rotate so >=8 loads are ALWAYS in flight during each
// accumulate phase (R7 had zero loads outstanding during its 48-FADD
// accumulate -> ~20% dead time, matching its 80.8% DRAM).
// ---------------------------------------------------------------------------

#define MAX_K 4096
#define ROWS_PER_WARP 8
#define ROWS_PER_BLOCK 32

__device__ int g_offsets[MAX_K + 1];

// 1-block Hillis-Steele inclusive scan of group_sizes (K <= 1024; K=1000 here).
__global__ void pgs_scan_kernel(const int* __restrict__ gs, int K) {
    __shared__ int sh[1024];
    int t = threadIdx.x;
    int v = (t < K) ? gs[t] : 0;
    sh[t] = v;
    __syncthreads();
#pragma unroll
    for (int off = 1; off < 1024; off <<= 1) {
        int add = (t >= off) ? sh[t - off] : 0;
        __syncthreads();
        sh[t] += add;
        __syncthreads();
    }
    if (t == 0) g_offsets[0] = 0;
    if (t < K) g_offsets[t + 1] = sh[t];
}

__device__ __forceinline__ float hsum4(float4 v) {
    return (v.x + v.y) + (v.z + v.w);
}

__global__ __launch_bounds__(128, 5) void pgs_sum_kernel(
    const float* __restrict__ x,
    float* __restrict__ out,
    int D, int K, int B)
{
    int g = blockIdx.x;
    int warp = threadIdx.x >> 5;
    int lane = threadIdx.x & 31;

    int row0 = blockIdx.y * ROWS_PER_BLOCK + warp * ROWS_PER_WARP;
    int nrows = B - row0;
    if (nrows <= 0) return;
    if (nrows > ROWS_PER_WARP) nrows = ROWS_PER_WARP;

    int s = g_offsets[g];
    int e = g_offsets[g + 1];

    const float* p = x + (size_t)row0 * (size_t)D;
    const size_t SD = (size_t)D;

    float acc[ROWS_PER_WARP];
#pragma unroll
    for (int r = 0; r < ROWS_PER_WARP; r++) acc[r] = 0.0f;

    int s4 = (s + 3) & ~3;
    int e4 = e & ~3;

#define LOAD8(buf, col)                                                        \
    _Pragma("unroll")                                                          \
    for (int r = 0; r < ROWS_PER_WARP; r++)                                    \
        buf[r] = __ldcs(reinterpret_cast<const float4*>(p + (size_t)r * SD + (col)));

#define ACC8(buf)                                                              \
    _Pragma("unroll")                                                          \
    for (int r = 0; r < ROWS_PER_WARP; r++)                                    \
        acc[r] += hsum4(buf[r]);

    if (nrows == ROWS_PER_WARP) {
        if (s4 >= e4) {
            // tiny group: scalar, coalesced across lanes, 8 streams
            for (int c = s + lane; c < e; c += 32) {
#pragma unroll
                for (int r = 0; r < ROWS_PER_WARP; r++)
                    acc[r] += __ldcs(p + (size_t)r * SD + c);
            }
        } else {
            // head (<=3 scalar cols)
            {
                int c = s + lane;
                if (c < s4) {
#pragma unroll
                    for (int r = 0; r < ROWS_PER_WARP; r++)
                        acc[r] += __ldcs(p + (size_t)r * SD + c);
                }
            }
            // software-pipelined main loop: loads of next tile in flight
            // during accumulation of the current tile.
            {
                int c4 = s4 + lane * 4;
                float4 v[ROWS_PER_WARP];
                float4 w[ROWS_PER_WARP];
                if (c4 < e4) {
                    LOAD8(v, c4);
                    int cn = c4 + 128;
                    while (cn < e4) {
                        LOAD8(w, cn);      // w in flight...
                        ACC8(v);           // ...while accumulating v
                        cn += 128;
                        if (cn < e4) {
                            LOAD8(v, cn);  // v' in flight...
                            ACC8(w);       // ...while accumulating w
                            cn += 128;
                        } else {
                            ACC8(w);
                            goto vec_done;
                        }
                    }
                    ACC8(v);
                vec_done: ;
                }
            }
            // tail (<=3 scalar cols)
            {
                int c = e4 + lane;
                if (c < e) {
#pragma unroll
                    for (int r = 0; r < ROWS_PER_WARP; r++)
                        acc[r] += __ldcs(p + (size_t)r * SD + c);
                }
            }
        }
    } else {
        // remainder rows (B not multiple of 32): scalar per-row path
        for (int r = 0; r < nrows; r++) {
            const float* pr = p + (size_t)r * SD;
            float a = 0.f;
            for (int c = s + lane; c < e; c += 32) a += __ldcs(pr + c);
            acc[r] = a;
        }
    }

#undef LOAD8
#undef ACC8

    // butterfly reduce all 8 accumulators
#pragma unroll
    for (int r = 0; r < ROWS_PER_WARP; r++) {
#pragma unroll
        for (int o = 16; o > 0; o >>= 1)
            acc[r] += __shfl_xor_sync(0xffffffffu, acc[r], o);
    }

    if (lane == 0) {
        const float inv_tau = 1.0f / 20.0f;
        size_t ob = (size_t)row0 * (size_t)K + g;
#pragma unroll
        for (int r = 0; r < ROWS_PER_WARP; r++)
            if (r < nrows) out[ob + (size_t)r * (size_t)K] = acc[r] * inv_tau;
    }
}

extern "C" void kernel_launch(void* const* d_in, const int* in_sizes, int n_in,
                              void* d_out, int out_size) {
    const float* x  = (const float*)d_in[0];
    const int*   gs = (const int*)d_in[1];

    int K = in_sizes[1];
    int B = out_size / K;
    int D = in_sizes[0] / B;

    float* out = (float*)d_out;

    pgs_scan_kernel<<<1, 1024>>>(gs, K);

    dim3 grid(K, (B + ROWS_PER_BLOCK - 1) / ROWS_PER_BLOCK);
    pgs_sum_kernel<<<grid, 128>>>(x, out, D, K, B);
}